// round 16
// baseline (speedup 1.0000x reference)
#include <cuda_runtime.h>
#include <math.h>
#include <stdint.h>

#define NT      8192        // tiles: bs(8) * n(32) * n(32)
#define NSM     148         // sm_100a
#define GRID    NSM         // 1 CTA/SM persistent
#define THREADS 512

static __device__ float g_P[64 * 256];   // P[pair][c]
static __device__ float g_A[NT * 256];   // A[t][c] (each CTA writes its own tiles)

// ---------------------------------------------------------------------------
// Kernel 1: P[p][c] = sum_d pe[p][d] * W[c][d]  (64 blocks, register-W form)
// ---------------------------------------------------------------------------
__global__ void __launch_bounds__(256) compute_P_kernel(const float* __restrict__ W)
{
    __shared__ float pe[64];
    const int tid = threadIdx.x;
    const int p   = blockIdx.x;

    float4 w4[16];
    const float4* wp = (const float4*)(W + tid * 64);
#pragma unroll
    for (int i = 0; i < 16; ++i) w4[i] = wp[i];

    if (tid < 32) {
        float div = expf(-(float)tid * 0.28782313662425572f);  // ln(1e4)/32
        float ang = (float)p * div;
        pe[2 * tid]     = sinf(ang);
        pe[2 * tid + 1] = cosf(ang);
    }
    __syncthreads();

    float a0 = 0.f, a1 = 0.f, a2 = 0.f, a3 = 0.f;
#pragma unroll
    for (int i = 0; i < 16; ++i) {
        a0 = fmaf(pe[4 * i + 0], w4[i].x, a0);
        a1 = fmaf(pe[4 * i + 1], w4[i].y, a1);
        a2 = fmaf(pe[4 * i + 2], w4[i].z, a2);
        a3 = fmaf(pe[4 * i + 3], w4[i].w, a3);
    }
    g_P[p * 256 + tid] = (a0 + a1) + (a2 + a3);
}

// ---------------------------------------------------------------------------
// Kernel 2: persistent kernel = in-CTA A prologue + R9's measured-best
// 2-deep TMA-bulk-store loop (no cache hint), with the TMA issue DISTRIBUTED
// across threads 0..7 (one 8KB run each; per-thread commit/wait groups).
//
// Loop (per tile t, index it; buffers = 2):
//   tid<8 : it>=2 -> cp.async.bulk.wait_group 1  (own group it-2 done)
//   sync                                          (=> bufs[it&1] free, all)
//   all   : prefetch a4/masks(t+1) ; compute ; STS -> bufs[it&1]
//   sync
//   tid<8 : fence.proxy.async ; cp.async.bulk (run tid) ; commit_group
//
// SMEM: 2 x 16384 floats (128 KB); buf0 doubles as prologue E scratch.
// ---------------------------------------------------------------------------
__global__ void __launch_bounds__(THREADS, 1) etoc_main_kernel(
    const float* __restrict__ E,
    const float* __restrict__ m1g,
    const float* __restrict__ m2g,
    const float* __restrict__ Wg,
    float* __restrict__ out)
{
    extern __shared__ float sm[];            // 2 * 16384 floats
    const int tid = threadIdx.x;
    const int bid = blockIdx.x;

    // ================= Prologue: A GEMM for own tiles =================
    const int Kt = (NT - bid + GRID - 1) / GRID;      // 55 or 56

    // Stage my E rows into scratch (sm[0 .. Kt*64)), coalesced per row.
    {
        const int nf4 = Kt * 16;
        for (int i = tid; i < nf4; i += THREADS) {
            int k = i >> 4, q = i & 15;
            ((float4*)sm)[k * 16 + q] =
                ((const float4*)(E + (size_t)(bid + k * GRID) * 64))[q];
        }
    }
    __syncthreads();

    {
        const int h  = tid >> 8;             // tile-range half (0/1)
        const int c  = tid & 255;
        const int k0 = h * 28;
        const int k1 = (Kt < k0 + 28) ? Kt : (k0 + 28);

        float4 w4[16];
        const float4* wp = (const float4*)(Wg + c * 64);
#pragma unroll
        for (int i = 0; i < 16; ++i) w4[i] = wp[i];

        for (int k = k0; k < k1; ++k) {
            const float4* e4 = (const float4*)(sm + k * 64);
            float a0 = 0.f, a1 = 0.f, a2 = 0.f, a3 = 0.f;
#pragma unroll
            for (int i = 0; i < 16; ++i) {
                float4 e = e4[i];
                a0 = fmaf(e.x, w4[i].x, a0);
                a1 = fmaf(e.y, w4[i].y, a1);
                a2 = fmaf(e.z, w4[i].z, a2);
                a3 = fmaf(e.w, w4[i].w, a3);
            }
            g_A[(size_t)(bid + k * GRID) * 256 + c] = (a0 + a1) + (a2 + a3);
        }
    }
    __syncthreads();   // g_A (own tiles) visible CTA-wide; scratch dead

    // ================= Main loop (R9 structure, distributed issue) ======
    const int cq  = tid & 63;                // float4 column (c/4)
    const int grp = tid >> 6;                // m2 index 0..7

    float4 Pr[8];
#pragma unroll
    for (int m1 = 0; m1 < 8; ++m1)
        Pr[m1] = *(const float4*)(g_P + (m1 * 8 + grp) * 256 + 4 * cq);

    int t = bid;
    int b = t >> 10, i1 = (t >> 5) & 31, j1 = t & 31;
    float4 a4  = *(const float4*)(g_A + (size_t)t * 256 + 4 * cq);
    float  m1v = __ldg(m1g + b * 32 + i1);
    float  m2v = __ldg(m2g + b * 32 + ((j1 * 8 + grp) & 31));

    int it = 0;
    while (true) {
        float* buf = sm + (it & 1) * 16384;

        // Buffer recycle: each issuing thread's group it-2 (last writer of
        // this buffer) must have drained. Collectively frees the buffer.
        if (tid < 8 && it >= 2)
            asm volatile("cp.async.bulk.wait_group 1;" ::: "memory");
        __syncthreads();

        // Prefetch next tile's A row + masks (in flight during STS phase)
        int  tn   = t + GRID;
        bool more = tn < NT;
        float4 a4n;
        float  m1n = 0.f, m2n = 0.f;
        if (more) {
            int bn = tn >> 10, i1n = (tn >> 5) & 31, j1n = tn & 31;
            a4n = *(const float4*)(g_A + (size_t)tn * 256 + 4 * cq);
            m1n = __ldg(m1g + bn * 32 + i1n);
            m2n = __ldg(m2g + bn * 32 + ((j1n * 8 + grp) & 31));
        }

        // Compute + STS 64KB. Layout mirrors GMEM runs: [m1][m2][c].
        float  f  = m1v * m2v;
        float4 fa = {f * a4.x, f * a4.y, f * a4.z, f * a4.w};
#pragma unroll
        for (int m1 = 0; m1 < 8; ++m1) {
            float4 p = Pr[m1];
            float4 v;
            v.x = fmaf(f, p.x, fa.x);
            v.y = fmaf(f, p.y, fa.y);
            v.z = fmaf(f, p.z, fa.z);
            v.w = fmaf(f, p.w, fa.w);
            *(float4*)(buf + m1 * 2048 + grp * 256 + 4 * cq) = v;
        }
        __syncthreads();

        // Distributed TMA issue: thread tid<8 owns run m1=tid (8KB).
        if (tid < 8) {
            asm volatile("fence.proxy.async.shared::cta;" ::: "memory");
            uint32_t s0;
            asm("{ .reg .u64 tt; cvta.to.shared.u64 tt, %1; cvt.u32.u64 %0, tt; }"
                : "=r"(s0) : "l"(buf));
            float* g0 = out +
                ((size_t)((b * 256 + i1 * 8) * 256 + j1 * 8)) * 256;
            asm volatile(
                "cp.async.bulk.global.shared::cta.bulk_group [%0], [%1], %2;"
                :: "l"(g0 + (size_t)tid * 65536), "r"(s0 + tid * 8192),
                   "r"(8192u)
                : "memory");
            asm volatile("cp.async.bulk.commit_group;" ::: "memory");
        }

        if (!more) break;
        t = tn;
        b = t >> 10; i1 = (t >> 5) & 31; j1 = t & 31;
        a4 = a4n; m1v = m1n; m2v = m2n;
        ++it;
    }

    // Drain all pending bulk stores before SMEM is released.
    if (tid < 8)
        asm volatile("cp.async.bulk.wait_group 0;" ::: "memory");
    __syncthreads();
}

// ---------------------------------------------------------------------------
// Launch
// ---------------------------------------------------------------------------
extern "C" void kernel_launch(void* const* d_in, const int* in_sizes, int n_in,
                              void* d_out, int out_size) {
    const float* E  = (const float*)d_in[0];  // (8,32,32,64)
    const float* m1 = (const float*)d_in[1];  // (8,32,1,1)
    const float* m2 = (const float*)d_in[2];  // (8,1,32,1)
    const float* W  = (const float*)d_in[3];  // (256,64)

    compute_P_kernel<<<64, 256>>>(W);

    size_t smem_bytes = 2 * 16384 * sizeof(float);   // 128 KB
    cudaFuncSetAttribute(etoc_main_kernel,
                         cudaFuncAttributeMaxDynamicSharedMemorySize,
                         (int)smem_bytes);
    etoc_main_kernel<<<GRID, THREADS, smem_bytes>>>(E, m1, m2, W, (float*)d_out);
}

// round 17
// speedup vs baseline: 1.0599x; 1.0599x over previous
#include <cuda_runtime.h>
#include <math.h>
#include <stdint.h>

#define NT   8192        // tiles: bs(8) * n(32) * n(32)
#define NSM  148         // sm_100a
#define GRID NSM         // 1 CTA/SM persistent

static __device__ float g_P[64 * 256];     // P[pair][c], pair = m1*8+m2

// ---------------------------------------------------------------------------
// Kernel 1: P[p][c] = sum_d pe[p][d] * W[c][d]   (64 blocks, ~2-3 us)
// ---------------------------------------------------------------------------
__global__ void __launch_bounds__(256) compute_P_kernel(const float* __restrict__ W)
{
    __shared__ float pe[64];
    const int tid = threadIdx.x;
    const int p   = blockIdx.x;

    float4 w4[16];
    const float4* wp = (const float4*)(W + tid * 64);
#pragma unroll
    for (int i = 0; i < 16; ++i) w4[i] = wp[i];

    if (tid < 32) {
        float div = expf(-(float)tid * 0.28782313662425572f); // ln(1e4)/32
        float ang = (float)p * div;
        pe[2 * tid]     = sinf(ang);
        pe[2 * tid + 1] = cosf(ang);
    }
    __syncthreads();

    float a0 = 0.f, a1 = 0.f, a2 = 0.f, a3 = 0.f;
#pragma unroll
    for (int i = 0; i < 16; ++i) {
        a0 = fmaf(pe[4 * i + 0], w4[i].x, a0);
        a1 = fmaf(pe[4 * i + 1], w4[i].y, a1);
        a2 = fmaf(pe[4 * i + 2], w4[i].z, a2);
        a3 = fmaf(pe[4 * i + 3], w4[i].w, a3);
    }
    g_P[p * 256 + tid] = (a0 + a1) + (a2 + a3);
}

// ---------------------------------------------------------------------------
// Kernel 2: R10's fused persistent kernel with ROLE-SPLIT overlap.
//   tid 0..255  : STS tile t (16 float4 each: m2 = grp2 and grp2+4)
//   tid 256..511: GEMV a(t+1) via SMEM Wt; tids 256..271 also roll the
//                 E(t+2) prefetch (LDG before GEMV, STS to ea after).
// Barrier/TMA structure IDENTICAL to R10 (best measured total 94.2us):
//   top: tid0 wait_group 1 (it>=2) ; sync
//   region: STS || GEMV || prefetch ; sync
//   tid0: fence + 8 x 8KB cp.async.bulk + commit
//
// SMEM (floats): Wt[0,16448) pad-257 W^T | ea[16448,16576) 2x64 |
//                av[16576,17088) 2x256 | bufs[17088,49856) 2x16384
// ---------------------------------------------------------------------------
__global__ void __launch_bounds__(512, 1) etoc_fused_kernel(
    const float* __restrict__ E,
    const float* __restrict__ m1g,
    const float* __restrict__ m2g,
    const float* __restrict__ Wg,
    float* __restrict__ out)
{
    extern __shared__ float sm[];
    float* Wt   = sm;                 // 64 * 257
    float* ea   = sm + 16448;         // 2 * 64
    float* av   = sm + 16576;         // 2 * 256
    float* bufs = sm + 17088;         // 2 * 16384

    const int tid = threadIdx.x;

    // Stage W transposed, pad-257 (coalesced LDG, conflict-free LDS).
    for (int idx = tid; idx < 16384; idx += 512) {
        int c = idx >> 6, d = idx & 63;
        Wt[d * 257 + c] = Wg[idx];
    }

    // STS-half thread coordinates + P slices (Pr[16]: m2 = grp2, grp2+4)
    const int cq   = tid & 63;        // float4 column (c/4)
    const int grp2 = (tid >> 6) & 3;  // 0..3
    float4 Pr[16];
    if (tid < 256) {
#pragma unroll
        for (int m1 = 0; m1 < 8; ++m1) {
            Pr[2 * m1 + 0] =
                *(const float4*)(g_P + (m1 * 8 + grp2)     * 256 + 4 * cq);
            Pr[2 * m1 + 1] =
                *(const float4*)(g_P + (m1 * 8 + grp2 + 4) * 256 + 4 * cq);
        }
    }

    int t = blockIdx.x;
    int b  = t >> 10, i1 = (t >> 5) & 31, j1 = t & 31;

    // Prologue 1: E row of t into ea[0]; masks of t (STS half only).
    if (tid < 16)
        ((float4*)ea)[tid] = ((const float4*)(E + t * 64))[tid];
    float m1v = 0.f, m2a = 0.f, m2b = 0.f;
    if (tid < 256) {
        m1v = __ldg(m1g + b * 32 + i1);
        m2a = __ldg(m2g + b * 32 + ((j1 * 8 + grp2) & 31));
        m2b = __ldg(m2g + b * 32 + ((j1 * 8 + grp2 + 4) & 31));
    }
    __syncthreads();

    // Prologue 2: GEMV(t) -> av[0]; E(t+1) -> ea[1]; masks of t+1.
    {
        int tn = t + GRID;
        if (tid < 256) {
            const float4* e4 = (const float4*)ea;
            float a0 = 0.f, a1 = 0.f, a2 = 0.f, a3 = 0.f;
#pragma unroll
            for (int i = 0; i < 16; ++i) {
                float4 e = e4[i];
                a0 = fmaf(e.x, Wt[(4 * i + 0) * 257 + tid], a0);
                a1 = fmaf(e.y, Wt[(4 * i + 1) * 257 + tid], a1);
                a2 = fmaf(e.z, Wt[(4 * i + 2) * 257 + tid], a2);
                a3 = fmaf(e.w, Wt[(4 * i + 3) * 257 + tid], a3);
            }
            av[tid] = (a0 + a1) + (a2 + a3);
        } else if (tn < NT && tid < 272) {
            ((float4*)(ea + 64))[tid - 256] =
                ((const float4*)(E + tn * 64))[tid - 256];
        }
    }
    float m1n = 0.f, m2an = 0.f, m2bn = 0.f;
    if (tid < 256 && t + GRID < NT) {
        int tn = t + GRID;
        int bn = tn >> 10, i1n = (tn >> 5) & 31, j1n = tn & 31;
        m1n  = __ldg(m1g + bn * 32 + i1n);
        m2an = __ldg(m2g + bn * 32 + ((j1n * 8 + grp2) & 31));
        m2bn = __ldg(m2g + bn * 32 + ((j1n * 8 + grp2 + 4) & 31));
    }

    int it = 0, cur = 0;
    while (true) {
        float* buf = bufs + (it & 1) * 16384;
        int  tn   = t + GRID;
        int  tnn  = t + 2 * GRID;
        bool more = tn < NT;

        // Buffer recycle: group it-2 (last writer of this buf) drained.
        if (tid == 0 && it >= 2)
            asm volatile("cp.async.bulk.wait_group 1;" ::: "memory");
        __syncthreads();

        float m1nn = 0.f, m2ann = 0.f, m2bnn = 0.f;

        if (tid < 256) {
            // ---------- STS half: tile t, 16 stores ----------
            float  fa = m1v * m2a;
            float  fb = m1v * m2b;
            float4 a4 = *(const float4*)(av + cur * 256 + 4 * cq);
            float4 aa = {fa * a4.x, fa * a4.y, fa * a4.z, fa * a4.w};
            float4 ab = {fb * a4.x, fb * a4.y, fb * a4.z, fb * a4.w};
#pragma unroll
            for (int m1 = 0; m1 < 8; ++m1) {
                float4 pa = Pr[2 * m1];
                float4 va;
                va.x = fmaf(fa, pa.x, aa.x);
                va.y = fmaf(fa, pa.y, aa.y);
                va.z = fmaf(fa, pa.z, aa.z);
                va.w = fmaf(fa, pa.w, aa.w);
                *(float4*)(buf + m1 * 2048 + grp2 * 256 + 4 * cq) = va;

                float4 pb = Pr[2 * m1 + 1];
                float4 vb;
                vb.x = fmaf(fb, pb.x, ab.x);
                vb.y = fmaf(fb, pb.y, ab.y);
                vb.z = fmaf(fb, pb.z, ab.z);
                vb.w = fmaf(fb, pb.w, ab.w);
                *(float4*)(buf + m1 * 2048 + (grp2 + 4) * 256 + 4 * cq) = vb;
            }
            // roll masks: prefetch t+2
            if (tnn < NT) {
                int bn = tnn >> 10, i1n = (tnn >> 5) & 31, j1n = tnn & 31;
                m1nn  = __ldg(m1g + bn * 32 + i1n);
                m2ann = __ldg(m2g + bn * 32 + ((j1n * 8 + grp2) & 31));
                m2bnn = __ldg(m2g + bn * 32 + ((j1n * 8 + grp2 + 4) & 31));
            }
        } else if (more) {
            // ---------- GEMV half: a(t+1), + E(t+2) prefetch ----------
            const int c = tid - 256;
            float4 ev;
            bool   pf = (tnn < NT) && (c < 16);
            if (pf)
                ev = ((const float4*)(E + tnn * 64))[c];  // LDG early

            const float4* e4 = (const float4*)(ea + (cur ^ 1) * 64);
            float a0 = 0.f, a1 = 0.f, a2 = 0.f, a3 = 0.f;
#pragma unroll
            for (int i = 0; i < 16; ++i) {
                float4 e = e4[i];
                a0 = fmaf(e.x, Wt[(4 * i + 0) * 257 + c], a0);
                a1 = fmaf(e.y, Wt[(4 * i + 1) * 257 + c], a1);
                a2 = fmaf(e.z, Wt[(4 * i + 2) * 257 + c], a2);
                a3 = fmaf(e.w, Wt[(4 * i + 3) * 257 + c], a3);
            }
            av[(cur ^ 1) * 256 + c] = (a0 + a1) + (a2 + a3);

            if (pf)
                ((float4*)(ea + cur * 64))[c] = ev;       // land prefetch
        }
        __syncthreads();   // buf complete, av[cur^1] + ea[cur] complete

        // ---- TMA issue for tile t (2-deep pipeline preserved) ----
        if (tid == 0) {
            asm volatile("fence.proxy.async.shared::cta;" ::: "memory");
            uint32_t s0;
            asm("{ .reg .u64 tt; cvta.to.shared.u64 tt, %1; cvt.u32.u64 %0, tt; }"
                : "=r"(s0) : "l"(buf));
            float* g0 = out +
                ((size_t)((b * 256 + i1 * 8) * 256 + j1 * 8)) * 256;
#pragma unroll
            for (int m1 = 0; m1 < 8; ++m1) {
                asm volatile(
                    "cp.async.bulk.global.shared::cta.bulk_group [%0], [%1], %2;"
                    :: "l"(g0 + (size_t)m1 * 65536), "r"(s0 + m1 * 8192),
                       "r"(8192u)
                    : "memory");
            }
            asm volatile("cp.async.bulk.commit_group;" ::: "memory");
        }

        if (!more) break;
        t = tn;
        b = t >> 10; i1 = (t >> 5) & 31; j1 = t & 31;
        m1v = m1n;  m2a = m2an;  m2b = m2bn;
        m1n = m1nn; m2an = m2ann; m2bn = m2bnn;
        cur ^= 1; ++it;
    }

    // Drain all pending bulk stores before SMEM is released.
    if (tid == 0)
        asm volatile("cp.async.bulk.wait_group 0;" ::: "memory");
    __syncthreads();
}

// ---------------------------------------------------------------------------
// Launch
// ---------------------------------------------------------------------------
extern "C" void kernel_launch(void* const* d_in, const int* in_sizes, int n_in,
                              void* d_out, int out_size) {
    const float* E  = (const float*)d_in[0];  // (8,32,32,64)
    const float* m1 = (const float*)d_in[1];  // (8,32,1,1)
    const float* m2 = (const float*)d_in[2];  // (8,1,32,1)
    const float* W  = (const float*)d_in[3];  // (256,64)

    compute_P_kernel<<<64, 256>>>(W);

    size_t smem_bytes = 49856 * sizeof(float);   // 199424 B
    cudaFuncSetAttribute(etoc_fused_kernel,
                         cudaFuncAttributeMaxDynamicSharedMemorySize,
                         (int)smem_bytes);
    etoc_fused_kernel<<<GRID, 512, smem_bytes>>>(E, m1, m2, W, (float*)d_out);
}